// round 15
// baseline (speedup 1.0000x reference)
#include <cuda_runtime.h>
#include <cuda_bf16.h>
#include <cuda_fp16.h>
#include <cstdint>

// Problem constants
#define BB   4
#define TT   32
#define NN   1000
#define CC   64
#define EE   16000
#define BT   (BB*TT)           // 128
#define BTN  (BT*NN)           // 128000
#define ELEM (BTN*CC)          // 8192000
#define EPSV 1e-5f

// ---------------- device scratch ---------------------------------------------
__device__ __align__(16) float g_xw[ELEM];   // x @ W (fp32)
__device__ __align__(16) __half g_xwh[ELEM]; // x @ W (fp16, for edge gathers)
__device__ __align__(16) float g_so[ELEM];   // GCN aggregate (pre-BN1)
__device__ __align__(16) float g_y2[ELEM];   // conv output (pre-BN2)
__device__ __align__(16) __nv_bfloat16 g_ah[ELEM];  // relu(bn1(so)) hi split
__device__ __align__(16) __nv_bfloat16 g_al[ELEM];  // lo split
__device__ __align__(16) __nv_bfloat16 g_wh[9 * CC * CC];  // conv [tap][c][ci] hi
__device__ __align__(16) __nv_bfloat16 g_wl[9 * CC * CC];  // lo
__device__ __align__(16) __nv_bfloat16 g_gwh[CC * CC];     // gcn W^T [d][ci] hi
__device__ __align__(16) __nv_bfloat16 g_gwl[CC * CC];     // lo
__device__ int   g_cnt[NN];       // zero at load; k_prep2 restores zero each call
__device__ int   g_off[NN + 1];
__device__ float g_dinv[NN];
__device__ __align__(8) int2 g_edge[EE];     // {src, nrm_bits}
__device__ float g_stats[4 * CC]; // [0:64)=s1 [64:128)=q1 [128:192)=s2 [192:256)=q2

// ---------------- warp-MMA helpers -------------------------------------------
__device__ __forceinline__ void ldsm4(uint32_t* r, const void* p) {
    uint32_t a = (uint32_t)__cvta_generic_to_shared(p);
    asm volatile("ldmatrix.sync.aligned.m8n8.x4.shared.b16 {%0,%1,%2,%3}, [%4];"
                 : "=r"(r[0]), "=r"(r[1]), "=r"(r[2]), "=r"(r[3]) : "r"(a));
}
__device__ __forceinline__ void ldsm2(uint32_t* r, const void* p) {
    uint32_t a = (uint32_t)__cvta_generic_to_shared(p);
    asm volatile("ldmatrix.sync.aligned.m8n8.x2.shared.b16 {%0,%1}, [%2];"
                 : "=r"(r[0]), "=r"(r[1]) : "r"(a));
}
__device__ __forceinline__ void mma_bf16(float* d, const uint32_t* a,
                                         const uint32_t* b) {
    asm volatile(
        "mma.sync.aligned.m16n8k16.row.col.f32.bf16.bf16.f32 "
        "{%0,%1,%2,%3}, {%4,%5,%6,%7}, {%8,%9}, {%0,%1,%2,%3};"
        : "+f"(d[0]), "+f"(d[1]), "+f"(d[2]), "+f"(d[3])
        : "r"(a[0]), "r"(a[1]), "r"(a[2]), "r"(a[3]), "r"(b[0]), "r"(b[1]));
}
__device__ __forceinline__ uint32_t pk(__nv_bfloat16 a, __nv_bfloat16 b) {
    __nv_bfloat162 t; t.x = a; t.y = b;
    return *reinterpret_cast<uint32_t*>(&t);
}
__device__ __forceinline__ void cpa16(void* dst, const void* src, int srcsize) {
    uint32_t d = (uint32_t)__cvta_generic_to_shared(dst);
    asm volatile("cp.async.cg.shared.global [%0], [%1], 16, %2;"
                 :: "r"(d), "l"(src), "r"(srcsize) : "memory");
}

// Shared tile geometry (rows padded to 144 B: 16B-aligned, conflict-free ldmatrix)
#define A_SPLIT_BYTES (128 * 144)                  // 18432
#define W_BASE        (2 * A_SPLIT_BYTES)          // 36864
#define W_SPLIT_BYTES (64 * 144)                   // 9216
#define TILE_SMEM     (W_BASE + 2 * W_SPLIT_BYTES) // 55296
#define CONV_SMEM     (2 * TILE_SMEM)              // 110592 (double buffer)

// ---------------- prep1: histogram (blocks 0-62) ∥ weights+stats (63+) ------
#define PREP1_GRID 104
__global__ void __launch_bounds__(256) k_prep1(const int* __restrict__ ei,
                                               const float* __restrict__ cw,
                                               const float* __restrict__ W) {
    int b = blockIdx.x;
    int tid = threadIdx.x;
    if (b < 63) {
        int e = b * 256 + tid;
        if (e < EE) atomicAdd(&g_cnt[ei[EE + e]], 1);
        return;
    }
#pragma unroll
    for (int j = 0; j < 4; j++) {
        int i = (b - 63) * 1024 + j * 256 + tid;
        if (i < 9 * CC * CC) {
            int tap = i >> 12;
            int c   = (i >> 6) & 63;
            int ci  = i & 63;
            float w = cw[(c * CC + ci) * 9 + tap];
            __nv_bfloat16 h = __float2bfloat16(w);
            g_wh[i] = h;
            g_wl[i] = __float2bfloat16(w - __bfloat162float(h));
        } else if (i < 9 * CC * CC + CC * CC) {
            int ii = i - 9 * CC * CC;
            int d  = ii >> 6;
            int ci = ii & 63;
            float w = W[ci * CC + d];     // transpose: [d][ci]
            __nv_bfloat16 h = __float2bfloat16(w);
            g_gwh[ii] = h;
            g_gwl[ii] = __float2bfloat16(w - __bfloat162float(h));
        } else if (i < 9 * CC * CC + CC * CC + 4 * CC) {
            g_stats[i - 9 * CC * CC - CC * CC] = 0.f;
        }
    }
}

// ---------------- prep2: scan + dinv + packed CSR fill (1 block) ------------
__global__ void __launch_bounds__(1024) k_prep2(const int* __restrict__ ei) {
    __shared__ int   s[1024];
    __shared__ int   scur[1024];
    __shared__ float sdinv[NN];
    int tid = threadIdx.x;
    int v = (tid < NN) ? g_cnt[tid] : 0;
    if (tid < NN) g_cnt[tid] = 0;           // restore zero invariant for replay
    s[tid] = v;
    for (int d = 1; d < 1024; d <<= 1) {
        __syncthreads();
        int t = (tid >= d) ? s[tid - d] : 0;
        __syncthreads();
        s[tid] += t;
    }
    __syncthreads();
    int excl = s[tid] - v;
    scur[tid] = excl;
    if (tid < NN) {
        g_off[tid] = excl;
        float dv = rsqrtf((float)(v + 1));
        sdinv[tid] = dv;
        g_dinv[tid] = dv;
    }
    if (tid == NN - 1) g_off[NN] = s[tid];
    __syncthreads();
#pragma unroll 4
    for (int e = tid; e < EE; e += 1024) {
        int sr = ei[e], ds = ei[EE + e];
        int pos = atomicAdd(&scur[ds], 1);
        g_edge[pos] = make_int2(sr, __float_as_int(sdinv[sr] * sdinv[ds]));
    }
}

// ---------------- xw = x @ W via MMA (in-kernel split conversion) -----------
__global__ void __launch_bounds__(256) k_xw_mma(const float* __restrict__ x) {
    extern __shared__ char smem[];
    int tid = threadIdx.x;
    int wid = tid >> 5;
    int lane = tid & 31;
    int r0 = blockIdx.x << 7;           // 1000 blocks
    int wm = wid >> 1, wn = wid & 1;

#pragma unroll
    for (int it = 0; it < 8; it++) {
        int id = tid + (it << 8);
        int row = id >> 4;
        int q = id & 15;
        float4 v = *reinterpret_cast<const float4*>(
            x + ((size_t)(r0 + row) << 6) + (q << 2));
        __nv_bfloat16 h0 = __float2bfloat16(v.x);
        __nv_bfloat16 h1 = __float2bfloat16(v.y);
        __nv_bfloat16 h2 = __float2bfloat16(v.z);
        __nv_bfloat16 h3 = __float2bfloat16(v.w);
        uint2 hh = make_uint2(pk(h0, h1), pk(h2, h3));
        uint2 ll = make_uint2(
            pk(__float2bfloat16(v.x - __bfloat162float(h0)),
               __float2bfloat16(v.y - __bfloat162float(h1))),
            pk(__float2bfloat16(v.z - __bfloat162float(h2)),
               __float2bfloat16(v.w - __bfloat162float(h3))));
        *reinterpret_cast<uint2*>(smem + row * 144 + q * 8) = hh;
        *reinterpret_cast<uint2*>(smem + A_SPLIT_BYTES + row * 144 + q * 8) = ll;
    }
#pragma unroll
    for (int it = 0; it < 4; it++) {
        int id = tid + (it << 8);
        int split = id >> 9;
        int rem = id & 511;
        int row = rem >> 3;
        int q = rem & 7;
        uint4 v = reinterpret_cast<const uint4*>(
            (split ? g_gwl : g_gwh) + (row << 6))[q];
        *reinterpret_cast<uint4*>(
            smem + W_BASE + split * W_SPLIT_BYTES + row * 144 + q * 16) = v;
    }
    __syncthreads();

    float acc[8][4];
#pragma unroll
    for (int f = 0; f < 8; f++)
#pragma unroll
        for (int j = 0; j < 4; j++) acc[f][j] = 0.f;

#pragma unroll
    for (int ks = 0; ks < 4; ks++) {
        int k0 = ks << 4;
        uint32_t ah[2][4], al[2][4];
        int ar = (lane & 15);
        int ac = k0 + ((lane >> 4) << 3);
#pragma unroll
        for (int mt = 0; mt < 2; mt++) {
            int row = wm * 32 + mt * 16 + ar;
            ldsm4(ah[mt], smem + row * 144 + ac * 2);
            ldsm4(al[mt], smem + A_SPLIT_BYTES + row * 144 + ac * 2);
        }
        uint32_t bh[4][2], bl[4][2];
        int br = (lane & 7);
        int bc = k0 + (((lane >> 3) & 1) << 3);
#pragma unroll
        for (int nt = 0; nt < 4; nt++) {
            int row = wn * 32 + nt * 8 + br;
            ldsm2(bh[nt], smem + W_BASE + row * 144 + bc * 2);
            ldsm2(bl[nt], smem + W_BASE + W_SPLIT_BYTES + row * 144 + bc * 2);
        }
#pragma unroll
        for (int mt = 0; mt < 2; mt++)
#pragma unroll
            for (int nt = 0; nt < 4; nt++) {
                float* d = acc[mt * 4 + nt];
                mma_bf16(d, ah[mt], bh[nt]);
                mma_bf16(d, al[mt], bh[nt]);
                mma_bf16(d, ah[mt], bl[nt]);
            }
    }
#pragma unroll
    for (int mt = 0; mt < 2; mt++)
#pragma unroll
        for (int nt = 0; nt < 4; nt++) {
            float* d = acc[mt * 4 + nt];
            int row = r0 + wm * 32 + mt * 16 + (lane >> 2);
            int col = wn * 32 + nt * 8 + ((lane & 3) << 1);
            *reinterpret_cast<float2*>(g_xw + ((size_t)row << 6) + col) =
                make_float2(d[0], d[1]);
            *reinterpret_cast<float2*>(g_xw + ((size_t)(row + 8) << 6) + col) =
                make_float2(d[2], d[3]);
            *reinterpret_cast<__half2*>(g_xwh + ((size_t)row << 6) + col) =
                __floats2half2_rn(d[0], d[1]);
            *reinterpret_cast<__half2*>(g_xwh + ((size_t)(row + 8) << 6) + col) =
                __floats2half2_rn(d[2], d[3]);
        }
}

// ---------------- GCN aggregation + fused BN1 stats (fp16 gathers) ----------
__global__ void __launch_bounds__(256) k_agg() {
    __shared__ float ss[8][CC], sq[8][CC];
    int tid = threadIdx.x;
    int wid = tid >> 5;
    int lane = tid & 31;
    float s0 = 0.f, s1v = 0.f, q0 = 0.f, q1 = 0.f;
    int base = (blockIdx.x << 6) + (wid << 3);

    for (int i = 0; i < 8; i++) {
        int idx = base + i;              // bt*NN + n
        int bt = idx / NN;
        int n  = idx - bt * NN;
        const __half* __restrict__ xwhb = g_xwh + (size_t)bt * NN * CC;

        float dv = g_dinv[n];
        float self_w = dv * dv;
        float2 v = *(const float2*)&g_xw[(size_t)bt * NN * CC + n * CC + lane * 2];
        float2 acc = make_float2(self_w * v.x, self_w * v.y);

        int e0 = g_off[n], e1 = g_off[n + 1];
        for (int e = e0; e < e1; e++) {
            int2 p = g_edge[e];
            __half2 uh = *(const __half2*)&xwhb[p.x * CC + lane * 2];
            float2 u = __half22float2(uh);
            float w = __int_as_float(p.y);
            acc.x += w * u.x;
            acc.y += w * u.y;
        }
        *(float2*)&g_so[idx * CC + lane * 2] = acc;
        s0 += acc.x; q0 += acc.x * acc.x;
        s1v += acc.y; q1 += acc.y * acc.y;
    }
    ss[wid][lane * 2] = s0;  ss[wid][lane * 2 + 1] = s1v;
    sq[wid][lane * 2] = q0;  sq[wid][lane * 2 + 1] = q1;
    __syncthreads();
    if (tid < CC) {
        float s = 0.f;
#pragma unroll
        for (int w = 0; w < 8; w++) s += ss[w][tid];
        atomicAdd(&g_stats[tid], s);
    } else if (tid < 2 * CC) {
        int c = tid - CC;
        float s = 0.f;
#pragma unroll
        for (int w = 0; w < 8; w++) s += sq[w][c];
        atomicAdd(&g_stats[CC + c], s);
    }
}

// ---------------- convert: relu(bn1(so)) -> bf16 hi/lo (inline BN1 final) ---
__global__ void k_cvt(const float* __restrict__ g1, const float* __restrict__ b1) {
    int i = blockIdx.x * blockDim.x + threadIdx.x;
    if (i < ELEM / 4) {
        int c = (i * 4) & 63;
        const float inv_n = 1.f / (float)BTN;
        float sc[4], tb[4];
#pragma unroll
        for (int j = 0; j < 4; j++) {
            float mean = g_stats[c + j] * inv_n;
            float var  = g_stats[CC + c + j] * inv_n - mean * mean;
            float s = g1[c + j] * rsqrtf(var + EPSV);
            sc[j] = s;
            tb[j] = b1[c + j] - mean * s;
        }
        float4 v = reinterpret_cast<const float4*>(g_so)[i];
        float r0 = fmaxf(v.x * sc[0] + tb[0], 0.f);
        float r1 = fmaxf(v.y * sc[1] + tb[1], 0.f);
        float r2 = fmaxf(v.z * sc[2] + tb[2], 0.f);
        float r3 = fmaxf(v.w * sc[3] + tb[3], 0.f);
        __nv_bfloat16 h0 = __float2bfloat16(r0);
        __nv_bfloat16 h1 = __float2bfloat16(r1);
        __nv_bfloat16 h2 = __float2bfloat16(r2);
        __nv_bfloat16 h3 = __float2bfloat16(r3);
        uint2 hh = make_uint2(pk(h0, h1), pk(h2, h3));
        reinterpret_cast<uint2*>(g_ah)[i] = hh;
        uint2 ll = make_uint2(
            pk(__float2bfloat16(r0 - __bfloat162float(h0)),
               __float2bfloat16(r1 - __bfloat162float(h1))),
            pk(__float2bfloat16(r2 - __bfloat162float(h2)),
               __float2bfloat16(r3 - __bfloat162float(h3))));
        reinterpret_cast<uint2*>(g_al)[i] = ll;
    }
}

// ---------------- conv tap load via cp.async ---------------------------------
__device__ __forceinline__ void conv_issue_tap(char* sbase, int btp, int tapk,
                                               int n0, int tid) {
#pragma unroll
    for (int it = 0; it < 8; it++) {
        int id = tid + (it << 8);
        int split = id >> 10;
        int rem = id & 1023;
        int row = rem >> 3;
        int q = rem & 7;
        int n = n0 + row;
        int ok = (n < NN);
        const __nv_bfloat16* gp = (split ? g_al : g_ah);
        const char* src = reinterpret_cast<const char*>(
            gp + (((size_t)btp * NN + (ok ? n : 0)) << 6)) + (q << 4);
        cpa16(sbase + split * A_SPLIT_BYTES + row * 144 + q * 16, src,
              ok ? 16 : 0);
    }
#pragma unroll
    for (int it = 0; it < 4; it++) {
        int id = tid + (it << 8);
        int split = id >> 9;
        int rem = id & 511;
        int row = rem >> 3;
        int q = rem & 7;
        const __nv_bfloat16* gp = (split ? g_wl : g_wh);
        const char* src = reinterpret_cast<const char*>(
            gp + ((tapk * CC + row) << 6)) + (q << 4);
        cpa16(sbase + W_BASE + split * W_SPLIT_BYTES + row * 144 + q * 16,
              src, 16);
    }
    asm volatile("cp.async.commit_group;" ::: "memory");
}

// ---------------- temporal conv: double-buffered cp.async + MMA + BN2 stats -
__global__ void __launch_bounds__(256) k_conv_mma() {
    extern __shared__ char smem[];
    int tid = threadIdx.x;
    int wid = tid >> 5;
    int lane = tid & 31;
    int tile = blockIdx.x;
    int bt = tile >> 3;
    int n0 = (tile & 7) << 7;
    int t = bt & 31;
    int btb = bt & ~31;
    int wm = wid >> 1, wn = wid & 1;

    float acc[8][4];
#pragma unroll
    for (int f = 0; f < 8; f++)
#pragma unroll
        for (int j = 0; j < 4; j++) acc[f][j] = 0.f;

    int tp0 = (t - 4 < 0) ? 0 : t - 4;
    int tp1 = (t + 4 > TT - 1) ? TT - 1 : t + 4;
    int ntaps = tp1 - tp0 + 1;

    // prologue: issue tap 0 into buffer 0
    conv_issue_tap(smem, btb + tp0, tp0 - t + 4, n0, tid);

    for (int i = 0; i < ntaps; i++) {
        char* sbase = smem + (i & 1) * TILE_SMEM;
        asm volatile("cp.async.wait_group 0;" ::: "memory");
        __syncthreads();
        if (i + 1 < ntaps) {
            int tp = tp0 + i + 1;
            conv_issue_tap(smem + ((i + 1) & 1) * TILE_SMEM,
                           btb + tp, tp - t + 4, n0, tid);
        }

#pragma unroll
        for (int ks = 0; ks < 4; ks++) {
            int k0 = ks << 4;
            uint32_t ah[2][4], al[2][4];
            int ar = (lane & 15);
            int ac = k0 + ((lane >> 4) << 3);
#pragma unroll
            for (int mt = 0; mt < 2; mt++) {
                int row = wm * 32 + mt * 16 + ar;
                ldsm4(ah[mt], sbase + row * 144 + ac * 2);
                ldsm4(al[mt], sbase + A_SPLIT_BYTES + row * 144 + ac * 2);
            }
            uint32_t bh[4][2], bl[4][2];
            int br = (lane & 7);
            int bc = k0 + (((lane >> 3) & 1) << 3);
#pragma unroll
            for (int nt = 0; nt < 4; nt++) {
                int row = wn * 32 + nt * 8 + br;
                ldsm2(bh[nt], sbase + W_BASE + row * 144 + bc * 2);
                ldsm2(bl[nt], sbase + W_BASE + W_SPLIT_BYTES + row * 144 + bc * 2);
            }
#pragma unroll
            for (int mt = 0; mt < 2; mt++)
#pragma unroll
                for (int nt = 0; nt < 4; nt++) {
                    float* d = acc[mt * 4 + nt];
                    mma_bf16(d, ah[mt], bh[nt]);
                    mma_bf16(d, al[mt], bh[nt]);
                    mma_bf16(d, ah[mt], bl[nt]);
                }
        }
    }

    // epilogue: write g_y2 + accumulate BN2 stats
    float cs[8], cq[8];
#pragma unroll
    for (int j = 0; j < 8; j++) { cs[j] = 0.f; cq[j] = 0.f; }

#pragma unroll
    for (int mt = 0; mt < 2; mt++) {
        int r0 = n0 + wm * 32 + mt * 16 + (lane >> 2);
        int r1 = r0 + 8;
        bool v0 = r0 < NN, v1 = r1 < NN;
#pragma unroll
        for (int nt = 0; nt < 4; nt++) {
            float* d = acc[mt * 4 + nt];
            int col = wn * 32 + nt * 8 + ((lane & 3) << 1);
            if (v0) {
                *reinterpret_cast<float2*>(
                    g_y2 + (((size_t)bt * NN + r0) << 6) + col) =
                    make_float2(d[0], d[1]);
                cs[nt * 2] += d[0];     cq[nt * 2] += d[0] * d[0];
                cs[nt * 2 + 1] += d[1]; cq[nt * 2 + 1] += d[1] * d[1];
            }
            if (v1) {
                *reinterpret_cast<float2*>(
                    g_y2 + (((size_t)bt * NN + r1) << 6) + col) =
                    make_float2(d[2], d[3]);
                cs[nt * 2] += d[2];     cq[nt * 2] += d[2] * d[2];
                cs[nt * 2 + 1] += d[3]; cq[nt * 2 + 1] += d[3] * d[3];
            }
        }
    }
#pragma unroll
    for (int off = 4; off < 32; off <<= 1) {
#pragma unroll
        for (int j = 0; j < 8; j++) {
            cs[j] += __shfl_xor_sync(0xffffffffu, cs[j], off);
            cq[j] += __shfl_xor_sync(0xffffffffu, cq[j], off);
        }
    }
    if ((lane >> 2) == 0) {
#pragma unroll
        for (int nt = 0; nt < 4; nt++)
#pragma unroll
            for (int h = 0; h < 2; h++) {
                int col = wn * 32 + nt * 8 + ((lane & 3) << 1) + h;
                atomicAdd(&g_stats[2 * CC + col], cs[nt * 2 + h]);
                atomicAdd(&g_stats[3 * CC + col], cq[nt * 2 + h]);
            }
    }
}

// ---------------- final: relu(bn2(y2) + x)  (inline BN2 finalize) -----------
__global__ void k_final(const float* __restrict__ x, float* __restrict__ out,
                        const float* __restrict__ g2, const float* __restrict__ b2) {
    int i = blockIdx.x * blockDim.x + threadIdx.x;
    if (i < ELEM / 4) {
        int c = (i * 4) & 63;
        const float inv_n = 1.f / (float)BTN;
        float sc[4], tb[4];
#pragma unroll
        for (int j = 0; j < 4; j++) {
            float mean = g_stats[2 * CC + c + j] * inv_n;
            float var  = g_stats[3 * CC + c + j] * inv_n - mean * mean;
            float s = g2[c + j] * rsqrtf(var + EPSV);
            sc[j] = s;
            tb[j] = b2[c + j] - mean * s;
        }
        float4 y = reinterpret_cast<const float4*>(g_y2)[i];
        float4 xv = reinterpret_cast<const float4*>(x)[i];
        float4 r;
        r.x = fmaxf(y.x * sc[0] + tb[0] + xv.x, 0.f);
        r.y = fmaxf(y.y * sc[1] + tb[1] + xv.y, 0.f);
        r.z = fmaxf(y.z * sc[2] + tb[2] + xv.z, 0.f);
        r.w = fmaxf(y.w * sc[3] + tb[3] + xv.w, 0.f);
        reinterpret_cast<float4*>(out)[i] = r;
    }
}

// ---------------- launch -----------------------------------------------------
extern "C" void kernel_launch(void* const* d_in, const int* in_sizes, int n_in,
                              void* d_out, int out_size) {
    const float* x  = (const float*)d_in[0];
    const int*   ei = (const int*)d_in[1];   // int32 (JAX x64 disabled)
    const float* W  = (const float*)d_in[2];
    const float* g1 = (const float*)d_in[4];
    const float* b1 = (const float*)d_in[5];
    const float* cw = (const float*)d_in[6];
    const float* g2 = (const float*)d_in[8];
    const float* b2 = (const float*)d_in[9];
    float* out = (float*)d_out;

    cudaFuncSetAttribute(k_conv_mma,
                         cudaFuncAttributeMaxDynamicSharedMemorySize, CONV_SMEM);
    cudaFuncSetAttribute(k_xw_mma,
                         cudaFuncAttributeMaxDynamicSharedMemorySize, TILE_SMEM);

    k_prep1<<<PREP1_GRID, 256>>>(ei, cw, W);
    k_prep2<<<1, 1024>>>(ei);
    k_xw_mma<<<BTN / 128, 256, TILE_SMEM>>>(x);
    k_agg<<<BTN / 64, 256>>>();
    k_cvt<<<(ELEM / 4 + 255) / 256, 256>>>(g1, b1);
    k_conv_mma<<<BT * 8, 256, CONV_SMEM>>>();
    k_final<<<(ELEM / 4 + 255) / 256, 256>>>(x, out, g2, b2);
}

// round 17
// speedup vs baseline: 1.1187x; 1.1187x over previous
#include <cuda_runtime.h>
#include <cuda_bf16.h>
#include <cstdint>

// Problem constants
#define BB   4
#define TT   32
#define NN   1000
#define CC   64
#define EE   16000
#define BT   (BB*TT)           // 128
#define BTN  (BT*NN)           // 128000
#define ELEM (BTN*CC)          // 8192000
#define EPSV 1e-5f

// ---------------- device scratch ---------------------------------------------
__device__ __align__(16) float g_xw[ELEM];   // x @ W
__device__ __align__(16) float g_so[ELEM];   // GCN aggregate (pre-BN1)
__device__ __align__(16) float g_y2[ELEM];   // conv output (pre-BN2)
__device__ __align__(16) __nv_bfloat16 g_ah[ELEM];  // relu(bn1(so)) hi split
__device__ __align__(16) __nv_bfloat16 g_al[ELEM];  // lo split
__device__ __align__(16) __nv_bfloat16 g_wh[9 * CC * CC];  // conv [tap][c][ci] hi
__device__ __align__(16) __nv_bfloat16 g_wl[9 * CC * CC];  // lo
__device__ __align__(16) __nv_bfloat16 g_gwh[CC * CC];     // gcn W^T [d][ci] hi
__device__ __align__(16) __nv_bfloat16 g_gwl[CC * CC];     // lo
__device__ int   g_cnt[NN];       // zero at load; k_prep2 restores zero each call
__device__ int   g_off[NN + 1];
__device__ float g_dinv[NN];
__device__ __align__(8) int2 g_edge[EE];     // {src, nrm_bits}
__device__ float g_stats[4 * CC]; // [0:64)=s1 [64:128)=q1 [128:192)=s2 [192:256)=q2

// ---------------- warp-MMA helpers -------------------------------------------
__device__ __forceinline__ void ldsm4(uint32_t* r, const void* p) {
    uint32_t a = (uint32_t)__cvta_generic_to_shared(p);
    asm volatile("ldmatrix.sync.aligned.m8n8.x4.shared.b16 {%0,%1,%2,%3}, [%4];"
                 : "=r"(r[0]), "=r"(r[1]), "=r"(r[2]), "=r"(r[3]) : "r"(a));
}
__device__ __forceinline__ void ldsm2(uint32_t* r, const void* p) {
    uint32_t a = (uint32_t)__cvta_generic_to_shared(p);
    asm volatile("ldmatrix.sync.aligned.m8n8.x2.shared.b16 {%0,%1}, [%2];"
                 : "=r"(r[0]), "=r"(r[1]) : "r"(a));
}
__device__ __forceinline__ void mma_bf16(float* d, const uint32_t* a,
                                         const uint32_t* b) {
    asm volatile(
        "mma.sync.aligned.m16n8k16.row.col.f32.bf16.bf16.f32 "
        "{%0,%1,%2,%3}, {%4,%5,%6,%7}, {%8,%9}, {%0,%1,%2,%3};"
        : "+f"(d[0]), "+f"(d[1]), "+f"(d[2]), "+f"(d[3])
        : "r"(a[0]), "r"(a[1]), "r"(a[2]), "r"(a[3]), "r"(b[0]), "r"(b[1]));
}
__device__ __forceinline__ uint32_t pk(__nv_bfloat16 a, __nv_bfloat16 b) {
    __nv_bfloat162 t; t.x = a; t.y = b;
    return *reinterpret_cast<uint32_t*>(&t);
}
__device__ __forceinline__ void cpa16(void* dst, const void* src, int srcsize) {
    uint32_t d = (uint32_t)__cvta_generic_to_shared(dst);
    asm volatile("cp.async.cg.shared.global [%0], [%1], 16, %2;"
                 :: "r"(d), "l"(src), "r"(srcsize) : "memory");
}

// Shared tile geometry (rows padded to 144 B: 16B-aligned, conflict-free ldmatrix)
#define A_SPLIT_BYTES (128 * 144)                  // 18432
#define W_BASE        (2 * A_SPLIT_BYTES)          // 36864
#define W_SPLIT_BYTES (64 * 144)                   // 9216
#define TILE_SMEM     (W_BASE + 2 * W_SPLIT_BYTES) // 55296
#define CONV_SMEM     (2 * TILE_SMEM)              // 110592 (double buffer)

// ---------------- prep1: histogram (blocks 0-62) ∥ weights+stats (63+) ------
#define PREP1_GRID 104
__global__ void __launch_bounds__(256) k_prep1(const int* __restrict__ ei,
                                               const float* __restrict__ cw,
                                               const float* __restrict__ W) {
    int b = blockIdx.x;
    int tid = threadIdx.x;
    if (b < 63) {
        int e = b * 256 + tid;
        if (e < EE) atomicAdd(&g_cnt[ei[EE + e]], 1);
        return;
    }
#pragma unroll
    for (int j = 0; j < 4; j++) {
        int i = (b - 63) * 1024 + j * 256 + tid;
        if (i < 9 * CC * CC) {
            int tap = i >> 12;
            int c   = (i >> 6) & 63;
            int ci  = i & 63;
            float w = cw[(c * CC + ci) * 9 + tap];
            __nv_bfloat16 h = __float2bfloat16(w);
            g_wh[i] = h;
            g_wl[i] = __float2bfloat16(w - __bfloat162float(h));
        } else if (i < 9 * CC * CC + CC * CC) {
            int ii = i - 9 * CC * CC;
            int d  = ii >> 6;
            int ci = ii & 63;
            float w = W[ci * CC + d];     // transpose: [d][ci]
            __nv_bfloat16 h = __float2bfloat16(w);
            g_gwh[ii] = h;
            g_gwl[ii] = __float2bfloat16(w - __bfloat162float(h));
        } else if (i < 9 * CC * CC + CC * CC + 4 * CC) {
            g_stats[i - 9 * CC * CC - CC * CC] = 0.f;
        }
    }
}

// ---------------- prep2: scan + dinv + packed CSR fill (1 block) ------------
__global__ void __launch_bounds__(1024) k_prep2(const int* __restrict__ ei) {
    __shared__ int   s[1024];
    __shared__ int   scur[1024];
    __shared__ float sdinv[NN];
    int tid = threadIdx.x;
    int v = (tid < NN) ? g_cnt[tid] : 0;
    if (tid < NN) g_cnt[tid] = 0;           // restore zero invariant for replay
    s[tid] = v;
    for (int d = 1; d < 1024; d <<= 1) {
        __syncthreads();
        int t = (tid >= d) ? s[tid - d] : 0;
        __syncthreads();
        s[tid] += t;
    }
    __syncthreads();
    int excl = s[tid] - v;
    scur[tid] = excl;
    if (tid < NN) {
        g_off[tid] = excl;
        float dv = rsqrtf((float)(v + 1));
        sdinv[tid] = dv;
        g_dinv[tid] = dv;
    }
    if (tid == NN - 1) g_off[NN] = s[tid];
    __syncthreads();
#pragma unroll 4
    for (int e = tid; e < EE; e += 1024) {
        int sr = ei[e], ds = ei[EE + e];
        int pos = atomicAdd(&scur[ds], 1);
        g_edge[pos] = make_int2(sr, __float_as_int(sdinv[sr] * sdinv[ds]));
    }
}

// ---------------- xw = x @ W via MMA (in-kernel split conversion) -----------
__global__ void __launch_bounds__(256) k_xw_mma(const float* __restrict__ x) {
    extern __shared__ char smem[];
    int tid = threadIdx.x;
    int wid = tid >> 5;
    int lane = tid & 31;
    int r0 = blockIdx.x << 7;           // 1000 blocks
    int wm = wid >> 1, wn = wid & 1;

#pragma unroll
    for (int it = 0; it < 8; it++) {
        int id = tid + (it << 8);
        int row = id >> 4;
        int q = id & 15;
        float4 v = *reinterpret_cast<const float4*>(
            x + ((size_t)(r0 + row) << 6) + (q << 2));
        __nv_bfloat16 h0 = __float2bfloat16(v.x);
        __nv_bfloat16 h1 = __float2bfloat16(v.y);
        __nv_bfloat16 h2 = __float2bfloat16(v.z);
        __nv_bfloat16 h3 = __float2bfloat16(v.w);
        uint2 hh = make_uint2(pk(h0, h1), pk(h2, h3));
        uint2 ll = make_uint2(
            pk(__float2bfloat16(v.x - __bfloat162float(h0)),
               __float2bfloat16(v.y - __bfloat162float(h1))),
            pk(__float2bfloat16(v.z - __bfloat162float(h2)),
               __float2bfloat16(v.w - __bfloat162float(h3))));
        *reinterpret_cast<uint2*>(smem + row * 144 + q * 8) = hh;
        *reinterpret_cast<uint2*>(smem + A_SPLIT_BYTES + row * 144 + q * 8) = ll;
    }
#pragma unroll
    for (int it = 0; it < 4; it++) {
        int id = tid + (it << 8);
        int split = id >> 9;
        int rem = id & 511;
        int row = rem >> 3;
        int q = rem & 7;
        uint4 v = reinterpret_cast<const uint4*>(
            (split ? g_gwl : g_gwh) + (row << 6))[q];
        *reinterpret_cast<uint4*>(
            smem + W_BASE + split * W_SPLIT_BYTES + row * 144 + q * 16) = v;
    }
    __syncthreads();

    float acc[8][4];
#pragma unroll
    for (int f = 0; f < 8; f++)
#pragma unroll
        for (int j = 0; j < 4; j++) acc[f][j] = 0.f;

#pragma unroll
    for (int ks = 0; ks < 4; ks++) {
        int k0 = ks << 4;
        uint32_t ah[2][4], al[2][4];
        int ar = (lane & 15);
        int ac = k0 + ((lane >> 4) << 3);
#pragma unroll
        for (int mt = 0; mt < 2; mt++) {
            int row = wm * 32 + mt * 16 + ar;
            ldsm4(ah[mt], smem + row * 144 + ac * 2);
            ldsm4(al[mt], smem + A_SPLIT_BYTES + row * 144 + ac * 2);
        }
        uint32_t bh[4][2], bl[4][2];
        int br = (lane & 7);
        int bc = k0 + (((lane >> 3) & 1) << 3);
#pragma unroll
        for (int nt = 0; nt < 4; nt++) {
            int row = wn * 32 + nt * 8 + br;
            ldsm2(bh[nt], smem + W_BASE + row * 144 + bc * 2);
            ldsm2(bl[nt], smem + W_BASE + W_SPLIT_BYTES + row * 144 + bc * 2);
        }
#pragma unroll
        for (int mt = 0; mt < 2; mt++)
#pragma unroll
            for (int nt = 0; nt < 4; nt++) {
                float* d = acc[mt * 4 + nt];
                mma_bf16(d, ah[mt], bh[nt]);
                mma_bf16(d, al[mt], bh[nt]);
                mma_bf16(d, ah[mt], bl[nt]);
            }
    }
#pragma unroll
    for (int mt = 0; mt < 2; mt++)
#pragma unroll
        for (int nt = 0; nt < 4; nt++) {
            float* d = acc[mt * 4 + nt];
            int row = r0 + wm * 32 + mt * 16 + (lane >> 2);
            int col = wn * 32 + nt * 8 + ((lane & 3) << 1);
            *reinterpret_cast<float2*>(g_xw + ((size_t)row << 6) + col) =
                make_float2(d[0], d[1]);
            *reinterpret_cast<float2*>(g_xw + ((size_t)(row + 8) << 6) + col) =
                make_float2(d[2], d[3]);
        }
}

// ---------------- GCN aggregation + fused BN1 stats (bt-grouped, MLP-4) -----
// Warp task: one node n x 4 consecutive bt slices. Edge metadata loaded once
// per 4 rows; the 4 gathers per edge are independent (MLP=4).
__global__ void __launch_bounds__(256) k_agg() {
    __shared__ float ss[8][CC], sq[8][CC];
    int tid = threadIdx.x;
    int wid = tid >> 5;
    int lane = tid & 31;
    int task = blockIdx.x * 8 + wid;     // 0..31999
    int n   = task % NN;
    int bt0 = (task / NN) << 2;          // 0,4,...,124
    int co = lane * 2;

    const float* __restrict__ xw0 = g_xw + ((size_t)bt0 * NN + n) * CC + co;
    const float* __restrict__ gb0 = g_xw + (size_t)bt0 * NN * CC + co;
    const size_t SL = (size_t)NN * CC;   // bt slice stride

    float dv = g_dinv[n];
    float self_w = dv * dv;
    float2 a0, a1, a2, a3;
    {
        float2 v0 = *(const float2*)(xw0);
        float2 v1 = *(const float2*)(xw0 + SL);
        float2 v2 = *(const float2*)(xw0 + 2 * SL);
        float2 v3 = *(const float2*)(xw0 + 3 * SL);
        a0 = make_float2(self_w * v0.x, self_w * v0.y);
        a1 = make_float2(self_w * v1.x, self_w * v1.y);
        a2 = make_float2(self_w * v2.x, self_w * v2.y);
        a3 = make_float2(self_w * v3.x, self_w * v3.y);
    }

    int e0 = g_off[n], e1 = g_off[n + 1];
    for (int e = e0; e < e1; e++) {
        int2 p = g_edge[e];
        const float* s = gb0 + (size_t)p.x * CC;
        float2 u0 = *(const float2*)(s);
        float2 u1 = *(const float2*)(s + SL);
        float2 u2 = *(const float2*)(s + 2 * SL);
        float2 u3 = *(const float2*)(s + 3 * SL);
        float w = __int_as_float(p.y);
        a0.x += w * u0.x; a0.y += w * u0.y;
        a1.x += w * u1.x; a1.y += w * u1.y;
        a2.x += w * u2.x; a2.y += w * u2.y;
        a3.x += w * u3.x; a3.y += w * u3.y;
    }

    float* so0 = g_so + ((size_t)bt0 * NN + n) * CC + co;
    *(float2*)(so0)          = a0;
    *(float2*)(so0 + SL)     = a1;
    *(float2*)(so0 + 2 * SL) = a2;
    *(float2*)(so0 + 3 * SL) = a3;

    float s0 = a0.x + a1.x + a2.x + a3.x;
    float s1v = a0.y + a1.y + a2.y + a3.y;
    float q0 = a0.x * a0.x + a1.x * a1.x + a2.x * a2.x + a3.x * a3.x;
    float q1 = a0.y * a0.y + a1.y * a1.y + a2.y * a2.y + a3.y * a3.y;

    ss[wid][co] = s0;  ss[wid][co + 1] = s1v;
    sq[wid][co] = q0;  sq[wid][co + 1] = q1;
    __syncthreads();
    if (tid < CC) {
        float s = 0.f;
#pragma unroll
        for (int w = 0; w < 8; w++) s += ss[w][tid];
        atomicAdd(&g_stats[tid], s);
    } else if (tid < 2 * CC) {
        int c = tid - CC;
        float s = 0.f;
#pragma unroll
        for (int w = 0; w < 8; w++) s += sq[w][c];
        atomicAdd(&g_stats[CC + c], s);
    }
}

// ---------------- convert: relu(bn1(so)) -> bf16 hi/lo (inline BN1 final) ---
__global__ void k_cvt(const float* __restrict__ g1, const float* __restrict__ b1) {
    int i = blockIdx.x * blockDim.x + threadIdx.x;
    if (i < ELEM / 4) {
        int c = (i * 4) & 63;
        const float inv_n = 1.f / (float)BTN;
        float sc[4], tb[4];
#pragma unroll
        for (int j = 0; j < 4; j++) {
            float mean = g_stats[c + j] * inv_n;
            float var  = g_stats[CC + c + j] * inv_n - mean * mean;
            float s = g1[c + j] * rsqrtf(var + EPSV);
            sc[j] = s;
            tb[j] = b1[c + j] - mean * s;
        }
        float4 v = reinterpret_cast<const float4*>(g_so)[i];
        float r0 = fmaxf(v.x * sc[0] + tb[0], 0.f);
        float r1 = fmaxf(v.y * sc[1] + tb[1], 0.f);
        float r2 = fmaxf(v.z * sc[2] + tb[2], 0.f);
        float r3 = fmaxf(v.w * sc[3] + tb[3], 0.f);
        __nv_bfloat16 h0 = __float2bfloat16(r0);
        __nv_bfloat16 h1 = __float2bfloat16(r1);
        __nv_bfloat16 h2 = __float2bfloat16(r2);
        __nv_bfloat16 h3 = __float2bfloat16(r3);
        uint2 hh = make_uint2(pk(h0, h1), pk(h2, h3));
        reinterpret_cast<uint2*>(g_ah)[i] = hh;
        uint2 ll = make_uint2(
            pk(__float2bfloat16(r0 - __bfloat162float(h0)),
               __float2bfloat16(r1 - __bfloat162float(h1))),
            pk(__float2bfloat16(r2 - __bfloat162float(h2)),
               __float2bfloat16(r3 - __bfloat162float(h3))));
        reinterpret_cast<uint2*>(g_al)[i] = ll;
    }
}

// ---------------- conv tap load via cp.async ---------------------------------
__device__ __forceinline__ void conv_issue_tap(char* sbase, int btp, int tapk,
                                               int n0, int tid) {
#pragma unroll
    for (int it = 0; it < 8; it++) {
        int id = tid + (it << 8);
        int split = id >> 10;
        int rem = id & 1023;
        int row = rem >> 3;
        int q = rem & 7;
        int n = n0 + row;
        int ok = (n < NN);
        const __nv_bfloat16* gp = (split ? g_al : g_ah);
        const char* src = reinterpret_cast<const char*>(
            gp + (((size_t)btp * NN + (ok ? n : 0)) << 6)) + (q << 4);
        cpa16(sbase + split * A_SPLIT_BYTES + row * 144 + q * 16, src,
              ok ? 16 : 0);
    }
#pragma unroll
    for (int it = 0; it < 4; it++) {
        int id = tid + (it << 8);
        int split = id >> 9;
        int rem = id & 511;
        int row = rem >> 3;
        int q = rem & 7;
        const __nv_bfloat16* gp = (split ? g_wl : g_wh);
        const char* src = reinterpret_cast<const char*>(
            gp + ((tapk * CC + row) << 6)) + (q << 4);
        cpa16(sbase + W_BASE + split * W_SPLIT_BYTES + row * 144 + q * 16,
              src, 16);
    }
    asm volatile("cp.async.commit_group;" ::: "memory");
}

// ---------------- temporal conv: double-buffered cp.async + MMA + BN2 stats -
__global__ void __launch_bounds__(256) k_conv_mma() {
    extern __shared__ char smem[];
    int tid = threadIdx.x;
    int wid = tid >> 5;
    int lane = tid & 31;
    int tile = blockIdx.x;
    int bt = tile >> 3;
    int n0 = (tile & 7) << 7;
    int t = bt & 31;
    int btb = bt & ~31;
    int wm = wid >> 1, wn = wid & 1;

    float acc[8][4];
#pragma unroll
    for (int f = 0; f < 8; f++)
#pragma unroll
        for (int j = 0; j < 4; j++) acc[f][j] = 0.f;

    int tp0 = (t - 4 < 0) ? 0 : t - 4;
    int tp1 = (t + 4 > TT - 1) ? TT - 1 : t + 4;
    int ntaps = tp1 - tp0 + 1;

    // prologue: issue tap 0 into buffer 0
    conv_issue_tap(smem, btb + tp0, tp0 - t + 4, n0, tid);

    for (int i = 0; i < ntaps; i++) {
        char* sbase = smem + (i & 1) * TILE_SMEM;
        asm volatile("cp.async.wait_group 0;" ::: "memory");
        __syncthreads();
        if (i + 1 < ntaps) {
            int tp = tp0 + i + 1;
            conv_issue_tap(smem + ((i + 1) & 1) * TILE_SMEM,
                           btb + tp, tp - t + 4, n0, tid);
        }

#pragma unroll
        for (int ks = 0; ks < 4; ks++) {
            int k0 = ks << 4;
            uint32_t ah[2][4], al[2][4];
            int ar = (lane & 15);
            int ac = k0 + ((lane >> 4) << 3);
#pragma unroll
            for (int mt = 0; mt < 2; mt++) {
                int row = wm * 32 + mt * 16 + ar;
                ldsm4(ah[mt], sbase + row * 144 + ac * 2);
                ldsm4(al[mt], sbase + A_SPLIT_BYTES + row * 144 + ac * 2);
            }
            uint32_t bh[4][2], bl[4][2];
            int br = (lane & 7);
            int bc = k0 + (((lane >> 3) & 1) << 3);
#pragma unroll
            for (int nt = 0; nt < 4; nt++) {
                int row = wn * 32 + nt * 8 + br;
                ldsm2(bh[nt], sbase + W_BASE + row * 144 + bc * 2);
                ldsm2(bl[nt], sbase + W_BASE + W_SPLIT_BYTES + row * 144 + bc * 2);
            }
#pragma unroll
            for (int mt = 0; mt < 2; mt++)
#pragma unroll
                for (int nt = 0; nt < 4; nt++) {
                    float* d = acc[mt * 4 + nt];
                    mma_bf16(d, ah[mt], bh[nt]);
                    mma_bf16(d, al[mt], bh[nt]);
                    mma_bf16(d, ah[mt], bl[nt]);
                }
        }
    }

    // epilogue: write g_y2 + accumulate BN2 stats
    float cs[8], cq[8];
#pragma unroll
    for (int j = 0; j < 8; j++) { cs[j] = 0.f; cq[j] = 0.f; }

#pragma unroll
    for (int mt = 0; mt < 2; mt++) {
        int r0 = n0 + wm * 32 + mt * 16 + (lane >> 2);
        int r1 = r0 + 8;
        bool v0 = r0 < NN, v1 = r1 < NN;
#pragma unroll
        for (int nt = 0; nt < 4; nt++) {
            float* d = acc[mt * 4 + nt];
            int col = wn * 32 + nt * 8 + ((lane & 3) << 1);
            if (v0) {
                *reinterpret_cast<float2*>(
                    g_y2 + (((size_t)bt * NN + r0) << 6) + col) =
                    make_float2(d[0], d[1]);
                cs[nt * 2] += d[0];     cq[nt * 2] += d[0] * d[0];
                cs[nt * 2 + 1] += d[1]; cq[nt * 2 + 1] += d[1] * d[1];
            }
            if (v1) {
                *reinterpret_cast<float2*>(
                    g_y2 + (((size_t)bt * NN + r1) << 6) + col) =
                    make_float2(d[2], d[3]);
                cs[nt * 2] += d[2];     cq[nt * 2] += d[2] * d[2];
                cs[nt * 2 + 1] += d[3]; cq[nt * 2 + 1] += d[3] * d[3];
            }
        }
    }
#pragma unroll
    for (int off = 4; off < 32; off <<= 1) {
#pragma unroll
        for (int j = 0; j < 8; j++) {
            cs[j] += __shfl_xor_sync(0xffffffffu, cs[j], off);
            cq[j] += __shfl_xor_sync(0xffffffffu, cq[j], off);
        }
    }
    if ((lane >> 2) == 0) {
#pragma unroll
        for (int nt = 0; nt < 4; nt++)
#pragma unroll
            for (int h = 0; h < 2; h++) {
                int col = wn * 32 + nt * 8 + ((lane & 3) << 1) + h;
                atomicAdd(&g_stats[2 * CC + col], cs[nt * 2 + h]);
                atomicAdd(&g_stats[3 * CC + col], cq[nt * 2 + h]);
            }
    }
}

// ---------------- final: relu(bn2(y2) + x)  (inline BN2 finalize) -----------
__global__ void k_final(const float* __restrict__ x, float* __restrict__ out,
                        const float* __restrict__ g2, const float* __restrict__ b2) {
    int i = blockIdx.x * blockDim.x + threadIdx.x;
    if (i < ELEM / 4) {
        int c = (i * 4) & 63;
        const float inv_n = 1.f / (float)BTN;
        float sc[4], tb[4];
#pragma unroll
        for (int j = 0; j < 4; j++) {
            float mean = g_stats[2 * CC + c + j] * inv_n;
            float var  = g_stats[3 * CC + c + j] * inv_n - mean * mean;
            float s = g2[c + j] * rsqrtf(var + EPSV);
            sc[j] = s;
            tb[j] = b2[c + j] - mean * s;
        }
        float4 y = reinterpret_cast<const float4*>(g_y2)[i];
        float4 xv = reinterpret_cast<const float4*>(x)[i];
        float4 r;
        r.x = fmaxf(y.x * sc[0] + tb[0] + xv.x, 0.f);
        r.y = fmaxf(y.y * sc[1] + tb[1] + xv.y, 0.f);
        r.z = fmaxf(y.z * sc[2] + tb[2] + xv.z, 0.f);
        r.w = fmaxf(y.w * sc[3] + tb[3] + xv.w, 0.f);
        reinterpret_cast<float4*>(out)[i] = r;
    }
}

// ---------------- launch -----------------------------------------------------
extern "C" void kernel_launch(void* const* d_in, const int* in_sizes, int n_in,
                              void* d_out, int out_size) {
    const float* x  = (const float*)d_in[0];
    const int*   ei = (const int*)d_in[1];   // int32 (JAX x64 disabled)
    const float* W  = (const float*)d_in[2];
    const float* g1 = (const float*)d_in[4];
    const float* b1 = (const float*)d_in[5];
    const float* cw = (const float*)d_in[6];
    const float* g2 = (const float*)d_in[8];
    const float* b2 = (const float*)d_in[9];
    float* out = (float*)d_out;

    cudaFuncSetAttribute(k_conv_mma,
                         cudaFuncAttributeMaxDynamicSharedMemorySize, CONV_SMEM);
    cudaFuncSetAttribute(k_xw_mma,
                         cudaFuncAttributeMaxDynamicSharedMemorySize, TILE_SMEM);

    k_prep1<<<PREP1_GRID, 256>>>(ei, cw, W);
    k_prep2<<<1, 1024>>>(ei);
    k_xw_mma<<<BTN / 128, 256, TILE_SMEM>>>(x);
    k_agg<<<4000, 256>>>();               // 32000 warp-tasks: n x 32 bt-groups
    k_cvt<<<(ELEM / 4 + 255) / 256, 256>>>(g1, b1);
    k_conv_mma<<<BT * 8, 256, CONV_SMEM>>>();
    k_final<<<(ELEM / 4 + 255) / 256, 256>>>(x, out, g2, b2);
}